// round 7
// baseline (speedup 1.0000x reference)
#include <cuda_runtime.h>
#include <math.h>
#include <stdint.h>

#define D 512
#define C 17
#define RMAX 131072
#define NBA 4096
#define NLOW 2048
#define CANDCAP 32768
#define TIECAP 512
#define LCAP 4096
#define CH2 64
#define SELBLK 136

// ---------------- device scratch (static; zero-init at module load) -------
__device__ unsigned g_entbits[RMAX];
__device__ int      g_cls[RMAX];
__device__ unsigned g_histA[C * NBA];    // re-zeroed in k_select phase 2
__device__ unsigned g_lowhist[C * NLOW]; // re-zeroed in k_select phase 2
__device__ unsigned g_prefA[C];
__device__ int      g_kleft[C];
__device__ int      g_cnt[C];
__device__ int      g_candcnt[C];
__device__ int      g_cand[C][CANDCAP];
__device__ int      g_list[(size_t)C * LCAP];
__device__ float    g_Wc[C * D];         // accumulated via global RED
__device__ float    g_rn[C];             // 1/norm per class
__device__ unsigned g_bar1, g_bar2;      // grid barriers (reset by k_sum)
__device__ unsigned g_done;              // k_sum completion counter

// ---- kernel 1: bank keys + new-row logits/entropy/argmax, hist pass A ----
__global__ void k_logits(const float* __restrict__ feat,
                         const float* __restrict__ w,
                         const float* __restrict__ bias,
                         const float* __restrict__ entbank,
                         const int*   __restrict__ labels,
                         int B, int N) {
    int tid = blockIdx.x * blockDim.x + threadIdx.x;
    int nth = gridDim.x * blockDim.x;
    for (int i = tid; i < N; i += nth) {
        unsigned bits = __float_as_uint(entbank[i]);  // entropies >= 0: monotone
        int c = labels[i];
        g_entbits[i] = bits;
        g_cls[i] = c;
        unsigned key = (unsigned)c * NBA + (bits >> 20);
        unsigned act = __activemask();
        unsigned peers = __match_any_sync(act, key);
        int leader = __ffs(peers) - 1;
        if ((threadIdx.x & 31) == leader)
            atomicAdd(&g_histA[key], (unsigned)__popc(peers));
    }

    int warp = tid >> 5;
    int lane = threadIdx.x & 31;
    if (warp >= B) return;

    const float* f = feat + (size_t)warp * D;
    float fv[16];
#pragma unroll
    for (int j = 0; j < 16; j++) fv[j] = f[lane + 32 * j];

    float s[C];
#pragma unroll
    for (int c = 0; c < C; c++) s[c] = 0.f;
#pragma unroll
    for (int j = 0; j < 16; j++) {
        float fj = fv[j];
#pragma unroll
        for (int c = 0; c < C; c++)
            s[c] += fj * __ldg(&w[(size_t)c * D + lane + 32 * j]);
    }
#pragma unroll
    for (int o = 16; o; o >>= 1) {
#pragma unroll
        for (int c = 0; c < C; c++)
            s[c] += __shfl_xor_sync(0xffffffffu, s[c], o);
    }
    float pc = -INFINITY;
#pragma unroll
    for (int c = 0; c < C; c++)
        if (lane == c) pc = s[c] + bias[c];

    float m = pc;
#pragma unroll
    for (int o = 16; o; o >>= 1) m = fmaxf(m, __shfl_xor_sync(0xffffffffu, m, o));

    float ex = (lane < C) ? expf(pc - m) : 0.f;
    float tt = (lane < C) ? ex * (pc - m) : 0.f;
    float S = ex, T = tt;
#pragma unroll
    for (int o = 16; o; o >>= 1) {
        S += __shfl_xor_sync(0xffffffffu, S, o);
        T += __shfl_xor_sync(0xffffffffu, T, o);
    }
    float ent = logf(S) - T / S;
    unsigned bal = __ballot_sync(0xffffffffu, (lane < C) && (pc == m));
    int amax = __ffs(bal) - 1;
    if (lane == 0) {
        unsigned bits = __float_as_uint(ent);
        g_entbits[N + warp] = bits;
        g_cls[N + warp] = amax;
        atomicAdd(&g_histA[amax * NBA + (bits >> 20)], 1u);
    }
}

// ---- grid barrier (all SELBLK blocks co-resident; reset by k_sum) --------
__device__ __forceinline__ void gridbar(unsigned* bar, unsigned target) {
    __syncthreads();
    if (threadIdx.x == 0) {
        __threadfence();
        atomicAdd(bar, 1u);
        while (*(volatile unsigned*)bar < target) {}
        __threadfence();
    }
    __syncthreads();
}

// ---- kernel 2 (fused): scanA -> compact -> selB ---------------------------
__global__ void __launch_bounds__(256, 1) k_select(const int* __restrict__ kptr, int R) {
    int bid = blockIdx.x;
    int t = threadIdx.x;  // 256

    __shared__ unsigned chunk[256];
    __shared__ unsigned incl[256];
    __shared__ int sh_thrbin, sh_kl2;
    __shared__ unsigned tkey[TIECAP];
    __shared__ int      tidx[TIECAP];
    __shared__ int      tcnt;
    __shared__ unsigned s_pref[C];

    // ---------------- phase 0: per-class scan of hist A -------------------
    if (bid < C) {
        int c = bid;
        const unsigned* h = &g_histA[c * NBA];
        unsigned s = 0;
#pragma unroll
        for (int j = 0; j < 16; j++) s += h[t * 16 + j];
        chunk[t] = s;
        incl[t] = s;
        __syncthreads();
#pragma unroll
        for (int off = 1; off < 256; off <<= 1) {
            unsigned v = (t >= off) ? incl[t - off] : 0u;
            __syncthreads();
            incl[t] += v;
            __syncthreads();
        }
        int tot = (int)incl[255];
        int Kf = kptr[0];
        int k = tot < Kf ? tot : Kf;
        if (t == 0) {
            g_cnt[c] = 0;
            g_candcnt[c] = 0;
            if (k <= 0) { g_prefA[c] = 0u; g_kleft[c] = 0; }
        }
        if (k > 0) {
            int excl = (int)incl[t] - (int)chunk[t];
            if ((int)incl[t] >= k && excl < k) {
                int run = excl;
                for (int q = 0; q < 16; q++) {
                    unsigned v = h[t * 16 + q];
                    if (run + (int)v >= k) {
                        g_prefA[c] = (unsigned)(t * 16 + q);
                        g_kleft[c] = k - run;
                        break;
                    }
                    run += (int)v;
                }
            }
        }
    } else {
        // idle blocks: zero the weight accumulator for k_sum's global REDs
        for (int i = (bid - C) * 256 + t; i < C * D; i += (SELBLK - C) * 256)
            g_Wc[i] = 0.f;
    }
    gridbar(&g_bar1, SELBLK);

    // ---------------- phase 1: compact (grid-stride over R) ---------------
    if (t < C) s_pref[t] = g_prefA[t];
    __syncthreads();
    {
        int tid = bid * 256 + t;
        int nth = SELBLK * 256;
        for (int i = tid; i < R; i += nth) {
            int c = g_cls[i];
            unsigned bits = g_entbits[i];
            unsigned b = bits >> 20;
            unsigned pa = s_pref[c];
            bool below = (b < pa);
            bool equal = (b == pa);
            unsigned act = __ballot_sync(0xffffffffu, below);
            if (below) {
                unsigned peers = __match_any_sync(act, c);
                int leader = __ffs(peers) - 1;
                int rank = __popc(peers & ((1u << (t & 31)) - 1u));
                int base = 0;
                if ((t & 31) == leader)
                    base = atomicAdd(&g_cnt[c], __popc(peers));
                base = __shfl_sync(peers, base, leader);
                g_list[(size_t)c * LCAP + base + rank] = i;
            }
            unsigned act2 = __ballot_sync(0xffffffffu, equal);
            if (equal) {
                unsigned peers = __match_any_sync(act2, c);
                int leader = __ffs(peers) - 1;
                int rank = __popc(peers & ((1u << (t & 31)) - 1u));
                int base = 0;
                if ((t & 31) == leader)
                    base = atomicAdd(&g_candcnt[c], __popc(peers));
                base = __shfl_sync(peers, base, leader);
                int p = base + rank;
                if (p < CANDCAP) g_cand[c][p] = i;
                atomicAdd(&g_lowhist[c * NLOW + ((bits >> 9) & 0x7FFu)], 1u);
            }
        }
    }
    gridbar(&g_bar2, SELBLK);

    // ---------------- phase 2: exact select per class ----------------------
    if (bid >= C) return;
    {
        int c = bid;
        int k = g_kleft[c];
        int m = g_candcnt[c]; if (m > CANDCAP) m = CANDCAP;
        const int* lst = g_cand[c];
        unsigned* lh = &g_lowhist[c * NLOW];

        if (k > 0 && m > 0) {
            unsigned s = 0;
#pragma unroll
            for (int j = 0; j < 8; j++) s += lh[t * 8 + j];
            chunk[t] = s;
            incl[t] = s;
            if (t == 0) tcnt = 0;
            __syncthreads();
#pragma unroll
            for (int off = 1; off < 256; off <<= 1) {
                unsigned v = (t >= off) ? incl[t - off] : 0u;
                __syncthreads();
                incl[t] += v;
                __syncthreads();
            }
            int excl = (int)incl[t] - (int)chunk[t];
            if ((int)incl[t] >= k && excl < k) {
                int run = excl;
                for (int q = 0; q < 8; q++) {
                    unsigned v = lh[t * 8 + q];
                    if (run + (int)v >= k) {
                        sh_thrbin = t * 8 + q;
                        sh_kl2 = k - run;
                        break;
                    }
                    run += (int)v;
                }
            }
            __syncthreads();
            int thrbin = sh_thrbin;
            int kl2 = sh_kl2;

            for (int j = t; j < m; j += 256) {
                int idx = lst[j];
                unsigned bits = g_entbits[idx];
                int lb = (int)((bits >> 9) & 0x7FFu);
                if (lb < thrbin) {
                    int p = atomicAdd(&g_cnt[c], 1);
                    g_list[(size_t)c * LCAP + p] = idx;
                } else if (lb == thrbin) {
                    int p = atomicAdd(&tcnt, 1);
                    if (p < TIECAP) { tkey[p] = bits; tidx[p] = idx; }
                }
            }
            __syncthreads();
            int tc = tcnt;
            if (tc <= TIECAP) {
                for (int j = t; j < tc; j += 256) {
                    unsigned key = tkey[j];
                    int idx = tidx[j];
                    int rank = 0;
                    for (int q = 0; q < tc; q++) {
                        unsigned kq = tkey[q];
                        rank += (kq < key) || (kq == key && tidx[q] < idx);
                    }
                    if (rank < kl2) {
                        int p = atomicAdd(&g_cnt[c], 1);
                        g_list[(size_t)c * LCAP + p] = idx;
                    }
                }
            } else {
                for (int j = t; j < m; j += 256) {
                    int idx = lst[j];
                    unsigned key = g_entbits[idx];
                    if ((int)((key >> 9) & 0x7FFu) != thrbin) continue;
                    int rank = 0;
                    for (int q = 0; q < m; q++) {
                        int iq = lst[q];
                        unsigned kq = g_entbits[iq];
                        if ((int)((kq >> 9) & 0x7FFu) != thrbin) continue;
                        rank += (kq < key) || (kq == key && iq < idx);
                    }
                    if (rank < kl2) {
                        int p = atomicAdd(&g_cnt[c], 1);
                        g_list[(size_t)c * LCAP + p] = idx;
                    }
                }
            }
        }
        // restore zero invariants for next run
        for (int i = t; i < NBA; i += 256) g_histA[c * NBA + i] = 0u;
        for (int i = t; i < NLOW; i += 256) g_lowhist[c * NLOW + i] = 0u;
    }
}

// ---- kernel 3: support sums -> global RED; last block computes norms -----
__global__ void k_sum(const float* __restrict__ supports,
                      const float* __restrict__ feat, int N) {
    int c = blockIdx.y;
    int blk = blockIdx.x;
    int cnt = g_cnt[c]; if (cnt > LCAP) cnt = LCAP;
    int w = threadIdx.x >> 5, lane = threadIdx.x & 31;
    int wg = blk * 8 + w;
    const int* lst = &g_list[(size_t)c * LCAP];

    float acc[16];
#pragma unroll
    for (int j = 0; j < 16; j++) acc[j] = 0.f;

    for (int idx = wg; idx < cnt; idx += CH2 * 8) {
        int r = lst[idx];
        const float4* p = (const float4*)((r < N) ? supports + (size_t)r * D
                                                  : feat + (size_t)(r - N) * D);
        float4 v[4];
        float ss = 0.f;
#pragma unroll
        for (int j = 0; j < 4; j++) {
            v[j] = p[lane + 32 * j];
            ss += v[j].x * v[j].x + v[j].y * v[j].y + v[j].z * v[j].z + v[j].w * v[j].w;
        }
#pragma unroll
        for (int o = 16; o; o >>= 1) ss += __shfl_xor_sync(0xffffffffu, ss, o);
        float rn = 1.f / fmaxf(sqrtf(ss), 1e-12f);
#pragma unroll
        for (int j = 0; j < 4; j++) {
            acc[4 * j + 0] += v[j].x * rn;
            acc[4 * j + 1] += v[j].y * rn;
            acc[4 * j + 2] += v[j].z * rn;
            acc[4 * j + 3] += v[j].w * rn;
        }
    }

    __shared__ float sacc[D];
    for (int d = threadIdx.x; d < D; d += blockDim.x) sacc[d] = 0.f;
    __syncthreads();
#pragma unroll
    for (int j = 0; j < 4; j++) {
        int d = 4 * (lane + 32 * j);
        atomicAdd(&sacc[d + 0], acc[4 * j + 0]);
        atomicAdd(&sacc[d + 1], acc[4 * j + 1]);
        atomicAdd(&sacc[d + 2], acc[4 * j + 2]);
        atomicAdd(&sacc[d + 3], acc[4 * j + 3]);
    }
    __syncthreads();
    // global reduction (REDG, no return)
    for (int d = threadIdx.x; d < D; d += blockDim.x)
        atomicAdd(&g_Wc[c * D + d], sacc[d]);

    // last-block: compute per-class inverse norms + reset sync words
    __shared__ int amlast;
    if (threadIdx.x == 0) {
        __threadfence();
        unsigned v = atomicAdd(&g_done, 1u);
        amlast = (v == (unsigned)(gridDim.x * gridDim.y - 1));
    }
    __syncthreads();
    if (!amlast) return;
    if (threadIdx.x == 0) { g_done = 0u; g_bar1 = 0u; g_bar2 = 0u; }
    __shared__ float red[8];
    __shared__ float sh_tot;
    for (int cc = 0; cc < C; cc++) {
        float v0 = g_Wc[cc * D + threadIdx.x];
        float v1 = g_Wc[cc * D + threadIdx.x + 256];
        float ss = v0 * v0 + v1 * v1;
#pragma unroll
        for (int o = 16; o; o >>= 1) ss += __shfl_xor_sync(0xffffffffu, ss, o);
        if ((threadIdx.x & 31) == 0) red[threadIdx.x >> 5] = ss;
        __syncthreads();
        if (threadIdx.x < 32) {
            float v = (threadIdx.x < 8) ? red[threadIdx.x] : 0.f;
#pragma unroll
            for (int o = 4; o; o >>= 1) v += __shfl_xor_sync(0xffffffffu, v, o);
            if (threadIdx.x == 0) sh_tot = v;
        }
        __syncthreads();
        if (threadIdx.x == 0)
            g_rn[cc] = 1.f / fmaxf(sqrtf(sh_tot), 1e-12f);
        __syncthreads();
    }
}

// ---- kernel 4: final GEMM out = feature @ (Wc * rn) -----------------------
__global__ void k_gemm2(const float* __restrict__ feat, float* __restrict__ out,
                        int B) {
    int tid = blockIdx.x * blockDim.x + threadIdx.x;
    int warp = tid >> 5;
    int lane = threadIdx.x & 31;
    if (warp >= B) return;
    const float* f = feat + (size_t)warp * D;
    float fv[16];
#pragma unroll
    for (int j = 0; j < 16; j++) fv[j] = f[lane + 32 * j];
    float s[C];
#pragma unroll
    for (int c = 0; c < C; c++) s[c] = 0.f;
#pragma unroll
    for (int j = 0; j < 16; j++) {
        float fj = fv[j];
#pragma unroll
        for (int c = 0; c < C; c++)
            s[c] += fj * g_Wc[c * D + lane + 32 * j];
    }
#pragma unroll
    for (int o = 16; o; o >>= 1) {
#pragma unroll
        for (int c = 0; c < C; c++)
            s[c] += __shfl_xor_sync(0xffffffffu, s[c], o);
    }
    float myv = 0.f;
#pragma unroll
    for (int c = 0; c < C; c++)
        if (lane == c) myv = s[c] * g_rn[c];
    if (lane < C) out[(size_t)warp * C + lane] = myv;
}

// ---- launch ---------------------------------------------------------------
extern "C" void kernel_launch(void* const* d_in, const int* in_sizes, int n_in,
                              void* d_out, int out_size) {
    const float* feature  = (const float*)d_in[0];
    const float* clf_w    = (const float*)d_in[1];
    const float* clf_b    = (const float*)d_in[2];
    const float* supports = (const float*)d_in[3];
    const float* ent_bank = (const float*)d_in[4];
    const int*   labels   = (const int*)d_in[5];
    const int*   kptr     = (const int*)d_in[6];

    int Cc = in_sizes[2];          // 17
    int Dv = in_sizes[1] / Cc;     // 512
    int B  = in_sizes[0] / Dv;     // 4096
    int N  = in_sizes[4];          // 100000
    int R  = N + B;
    (void)n_in; (void)out_size; (void)Dv;

    float* out = (float*)d_out;

    int blk1 = (B * 32 + 255) / 256;
    k_logits<<<blk1, 256>>>(feature, clf_w, clf_b, ent_bank, labels, B, N);
    k_select<<<SELBLK, 256>>>(kptr, R);
    dim3 g3(CH2, C);
    k_sum<<<g3, 256>>>(supports, feature, N);
    k_gemm2<<<blk1, 256>>>(feature, out, B);
}